// round 16
// baseline (speedup 1.0000x reference)
#include <cuda_runtime.h>
#include <cuda_fp16.h>
#include <cstdint>

// Problem dims
#define B_   32
#define T_   128
#define E_   4096
#define H_   32
#define DK_  128
#define F_   16384
#define BT_  (B_*T_)

// ---------------- scratch (device globals: allocation-free rule) ----------
__device__ float  g_q   [(size_t)BT_*E_];
__device__ float  g_k   [(size_t)BT_*E_];
__device__ float  g_tmp [(size_t)BT_*E_];
__device__ float  g_x1  [(size_t)BT_*E_];
__device__ __half g_xh  [(size_t)BT_*E_];
__device__ __half g_attnh[(size_t)BT_*E_];  // attention probs, (B,T,H*T) layout, fp16
__device__ __half g_x1h [(size_t)BT_*E_];
__device__ __half g_hh  [(size_t)BT_*F_];
__device__ __half g_wqh [(size_t)E_*E_];
__device__ __half g_wkh [(size_t)E_*E_];
__device__ __half g_woh [(size_t)E_*E_];
__device__ __half g_w1h [(size_t)E_*F_];
__device__ __half g_w2h [(size_t)F_*E_];

// ======================= low-level helpers =================================
__device__ __forceinline__ unsigned smem_u32(const void* p) {
    return (unsigned)__cvta_generic_to_shared(p);
}
__device__ __forceinline__ void cp_async16(unsigned dst, const void* src) {
    asm volatile("cp.async.cg.shared.global [%0], [%1], 16;\n" :: "r"(dst), "l"(src));
}
__device__ __forceinline__ void cp_commit() {
    asm volatile("cp.async.commit_group;\n" ::: "memory");
}
template<int N> __device__ __forceinline__ void cp_wait() {
    asm volatile("cp.async.wait_group %0;\n" :: "n"(N) : "memory");
}
__device__ __forceinline__ void ldsm4(unsigned* r, unsigned addr) {
    asm volatile("ldmatrix.sync.aligned.m8n8.x4.shared.b16 {%0,%1,%2,%3}, [%4];"
        : "=r"(r[0]), "=r"(r[1]), "=r"(r[2]), "=r"(r[3]) : "r"(addr));
}
__device__ __forceinline__ void ldsm4t(unsigned* r, unsigned addr) {
    asm volatile("ldmatrix.sync.aligned.m8n8.x4.trans.shared.b16 {%0,%1,%2,%3}, [%4];"
        : "=r"(r[0]), "=r"(r[1]), "=r"(r[2]), "=r"(r[3]) : "r"(addr));
}
__device__ __forceinline__ void mma16816(float* c, const unsigned* a, const unsigned* b) {
    asm volatile("mma.sync.aligned.m16n8k16.row.col.f32.f16.f16.f32 "
        "{%0,%1,%2,%3}, {%4,%5,%6,%7}, {%8,%9}, {%0,%1,%2,%3};"
        : "+f"(c[0]), "+f"(c[1]), "+f"(c[2]), "+f"(c[3])
        : "r"(a[0]), "r"(a[1]), "r"(a[2]), "r"(a[3]), "r"(b[0]), "r"(b[1]));
}
__device__ __forceinline__ unsigned sw128(unsigned o) { return o ^ ((o >> 3) & 0x70); }

// ======================= fp16 GEMM =========================================
// D[M,N] = A_h[M,K] @ W_h[K,N] (+bias fp32; EPI variants). fp32 accumulate.
// CTA tile 128x256, BK=64, 512 threads = 16 warps in 2(M)x8(N) grid of 64x32.
// SMEM: A stage 128rows x 128B (sw128), B stage 4 nh-blocks x [64rows x 128B].
// EPI: 0 = +bias, scatter fp32 to (B,H,T,DK); 1 = relu(+bias) -> fp16;
//      2 = +bias+resid(fp32) -> fp32
#define SA_SZ 16384
#define SB_SZ 32768
#define SB_BASE (3*SA_SZ)
#define GSMEM (3*SA_SZ + 3*SB_SZ)     // 147456 B

template<int EPI>
__global__ void __launch_bounds__(512, 1) hgemm(
    const __half* __restrict__ A, const __half* __restrict__ W,
    const float* __restrict__ bias, const float* __restrict__ resid,
    void* __restrict__ outp, int M, int N, int K)
{
    extern __shared__ char smem[];
    const unsigned sbase = smem_u32(smem);
    const int tid = threadIdx.x, wid = tid >> 5, lane = tid & 31;
    const int m0 = blockIdx.x * 128, n0 = blockIdx.y * 256;
    const int wm = (wid >> 3) * 64, wn = (wid & 7) * 32;
    const int KT = K >> 6;

    auto load_stage = [&](int s, int kt) {
        const int k0 = kt << 6;
        const unsigned sA = sbase + s*SA_SZ;
        const unsigned sB = sbase + SB_BASE + s*SB_SZ;
        #pragma unroll
        for (int i = 0; i < 2; i++) {               // A: 1024 granules of 16B
            int gid = tid + i*512;
            int row = gid >> 3, g = gid & 7;
            cp_async16(sA + sw128((row << 7) + (g << 4)),
                       A + (size_t)(m0 + row)*K + k0 + g*8);
        }
        #pragma unroll
        for (int i = 0; i < 4; i++) {               // B: 2048 granules
            int gid = tid + i*512;
            int k = gid >> 5, gg = gid & 31, nh = gg >> 3, g = gg & 7;
            cp_async16(sB + (nh << 13) + sw128((k << 7) + (g << 4)),
                       W + (size_t)(k0 + k)*N + n0 + nh*64 + g*8);
        }
        cp_commit();
    };

    float acc[4][4][4];
    #pragma unroll
    for (int mi = 0; mi < 4; mi++)
        #pragma unroll
        for (int ni = 0; ni < 4; ni++)
            #pragma unroll
            for (int r = 0; r < 4; r++) acc[mi][ni][r] = 0.f;

    load_stage(0, 0);
    load_stage(1, 1);

    // precomputed lane pieces for ldmatrix addressing
    const int l8  = (lane & 7) + ((lane >> 3) & 1) * 8;   // row within 16
    const int sel = (lane >> 4) & 1;                       // 0/1 -> +8 halves

    for (int kt = 0; kt < KT; kt++) {
        cp_wait<1>();
        __syncthreads();
        const int s = kt % 3;
        const unsigned sA = sbase + s*SA_SZ;
        const unsigned sB = sbase + SB_BASE + s*SB_SZ + ((wn >> 6) << 13);

        #pragma unroll
        for (int ks = 0; ks < 4; ks++) {
            unsigned a[4][4], bq[2][4];
            #pragma unroll
            for (int mi = 0; mi < 4; mi++) {
                int arow = wm + mi*16 + l8;
                int acol = ks*32 + sel*16;               // bytes
                ldsm4(a[mi], sA + sw128((arow << 7) + acol));
            }
            #pragma unroll
            for (int np = 0; np < 2; np++) {
                int brow = ks*16 + l8;
                int bcol = ((wn & 63) + np*16 + sel*8) * 2;  // bytes
                ldsm4t(bq[np], sB + sw128((brow << 7) + bcol));
            }
            #pragma unroll
            for (int mi = 0; mi < 4; mi++)
                #pragma unroll
                for (int ni = 0; ni < 4; ni++)
                    mma16816(acc[mi][ni], a[mi], &bq[ni >> 1][(ni & 1) * 2]);
        }
        if (kt + 2 < KT) load_stage((kt + 2) % 3, kt + 2);
        else cp_commit();
    }

    // ---------------- epilogue (register accs -> GMEM) ---------------------
    const int g = lane >> 2, tig = lane & 3;
    #pragma unroll
    for (int mi = 0; mi < 4; mi++) {
        #pragma unroll
        for (int ni = 0; ni < 4; ni++) {
            const int n = n0 + wn + ni*8 + 2*tig;
            const float2 bz = *(const float2*)(bias + n);
            #pragma unroll
            for (int hh = 0; hh < 2; hh++) {
                const int m = m0 + wm + mi*16 + g + hh*8;
                float v0 = acc[mi][ni][hh*2 + 0] + bz.x;
                float v1 = acc[mi][ni][hh*2 + 1] + bz.y;
                if (EPI == 0) {
                    // scatter (b,t | h,dk) -> (B,H,T,DK) fp32
                    size_t o = (((size_t)((m >> 7)*H_ + (n >> 7))*T_ + (m & 127)) << 7) + (n & 127);
                    *(float2*)((float*)outp + o) = make_float2(v0, v1);
                } else if (EPI == 1) {
                    __half2 hv = __floats2half2_rn(fmaxf(v0, 0.f), fmaxf(v1, 0.f));
                    *(__half2*)((__half*)outp + (size_t)m*N + n) = hv;
                } else {
                    size_t o = (size_t)m*N + n;
                    float2 r = *(const float2*)(resid + o);
                    *(float2*)((float*)outp + o) = make_float2(v0 + r.x, v1 + r.y);
                }
            }
        }
    }
}

// ================= fp32 -> fp16 convert ====================================
__global__ void __launch_bounds__(256) f2h(const float* __restrict__ in,
                                           __half* __restrict__ out, int n8)
{
    int i = blockIdx.x * 256 + threadIdx.x;
    if (i >= n8) return;
    const float4* p = (const float4*)(in + (size_t)i*8);
    float4 u = p[0], v = p[1];
    __half2 h0 = __floats2half2_rn(u.x, u.y);
    __half2 h1 = __floats2half2_rn(u.z, u.w);
    __half2 h2 = __floats2half2_rn(v.x, v.y);
    __half2 h3 = __floats2half2_rn(v.z, v.w);
    uint4 o;
    o.x = *(unsigned*)&h0; o.y = *(unsigned*)&h1;
    o.z = *(unsigned*)&h2; o.w = *(unsigned*)&h3;
    *(uint4*)(out + (size_t)i*8) = o;
}

// ================= attention: scores (tf32 mma.sync) + softmax =============
// q,k fp32 (B,H,T,DK); output fp16 probs in (B,T,H*T) layout.
#define ATTN_SMEM (2*128*132*4)
__device__ __forceinline__ void mma_tf32_frag(float* c, const unsigned* a, const unsigned* b) {
    asm volatile(
        "mma.sync.aligned.m16n8k8.row.col.f32.tf32.tf32.f32 "
        "{%0,%1,%2,%3}, {%4,%5,%6,%7}, {%8,%9}, {%0,%1,%2,%3};\n"
        : "+f"(c[0]), "+f"(c[1]), "+f"(c[2]), "+f"(c[3])
        : "r"(a[0]), "r"(a[1]), "r"(a[2]), "r"(a[3]), "r"(b[0]), "r"(b[1]));
}

__global__ void __launch_bounds__(256) attn_kernel(
    const float* __restrict__ q, const float* __restrict__ k, __half* __restrict__ attn)
{
    extern __shared__ float fsm[];
    float* qs = fsm;             // [128][132]
    float* ks = fsm + 128*132;   // [128][132]
    const int bh = blockIdx.x;
    const int b = bh >> 5, h = bh & 31;
    const float* qg = q + (size_t)bh * 16384;
    const float* kg = k + (size_t)bh * 16384;
    const int tid = threadIdx.x;

    for (int i = tid; i < 4096; i += 256) {
        int row = i >> 5, c4 = (i & 31) << 2;
        *(float4*)(qs + row*132 + c4) = *(const float4*)(qg + row*128 + c4);
        *(float4*)(ks + row*132 + c4) = *(const float4*)(kg + row*128 + c4);
    }
    __syncthreads();

    const int warp = tid >> 5, lane = tid & 31, g = lane >> 2, tig = lane & 3;
    const int rbase = warp * 16;

    float acc[16][4];
    #pragma unroll
    for (int ni = 0; ni < 16; ni++)
        #pragma unroll
        for (int r = 0; r < 4; r++) acc[ni][r] = 0.f;

    #pragma unroll
    for (int kk = 0; kk < 16; ++kk) {
        const int kb = kk * 8;
        unsigned a[4];
        a[0] = __float_as_uint(qs[(rbase + g)*132 + kb + tig]);
        a[1] = __float_as_uint(qs[(rbase + g + 8)*132 + kb + tig]);
        a[2] = __float_as_uint(qs[(rbase + g)*132 + kb + tig + 4]);
        a[3] = __float_as_uint(qs[(rbase + g + 8)*132 + kb + tig + 4]);
        #pragma unroll
        for (int ni = 0; ni < 16; ++ni) {
            int c = ni*8 + g;
            unsigned bfr[2];
            bfr[0] = __float_as_uint(ks[c*132 + kb + tig]);
            bfr[1] = __float_as_uint(ks[c*132 + kb + tig + 4]);
            mma_tf32_frag(acc[ni], a, bfr);
        }
    }

    #pragma unroll
    for (int ni = 0; ni < 16; ni++) {
        int c = ni*8 + 2*tig;
        qs[(rbase + g)*132 + c]       = acc[ni][0];
        qs[(rbase + g)*132 + c + 1]   = acc[ni][1];
        qs[(rbase + g + 8)*132 + c]   = acc[ni][2];
        qs[(rbase + g + 8)*132 + c+1] = acc[ni][3];
    }
    __syncwarp();

    const float SCALE = 0.0883883476483184406f;   // 1/sqrt(128)
    for (int r = 0; r < 16; ++r) {
        int row = rbase + r;
        float v0 = qs[row*132 + lane]      * SCALE;
        float v1 = qs[row*132 + lane + 32] * SCALE;
        float v2 = qs[row*132 + lane + 64] * SCALE;
        float v3 = qs[row*132 + lane + 96] * SCALE;
        float mx = fmaxf(fmaxf(v0, v1), fmaxf(v2, v3));
        #pragma unroll
        for (int off = 16; off; off >>= 1) mx = fmaxf(mx, __shfl_xor_sync(~0u, mx, off));
        float e0 = __expf(v0 - mx), e1 = __expf(v1 - mx), e2 = __expf(v2 - mx), e3 = __expf(v3 - mx);
        float s = e0 + e1 + e2 + e3;
        #pragma unroll
        for (int off = 16; off; off >>= 1) s += __shfl_xor_sync(~0u, s, off);
        float inv = __frcp_rn(s);
        // (B,T,H,T') layout, fp16
        __half* o = attn + (((size_t)(b*T_ + row)*H_ + h) << 7);
        o[lane]      = __float2half_rn(e0*inv);
        o[lane + 32] = __float2half_rn(e1*inv);
        o[lane + 64] = __float2half_rn(e2*inv);
        o[lane + 96] = __float2half_rn(e3*inv);
    }
}

// ---------------- layernorm (one CTA per token) ----------------------------
// WH=1: additionally write fp16 copy (for the next GEMM's A operand).
template<int WH>
__global__ void __launch_bounds__(256) ln_kernel(
    const float* __restrict__ in, const float* __restrict__ gam,
    const float* __restrict__ bet, float* __restrict__ out, __half* __restrict__ outh)
{
    __shared__ float red[2][8];
    const int row = blockIdx.x;
    const float* src = in + (size_t)row * E_;
    float4 v[4];
    float s = 0.f, sq = 0.f;
    #pragma unroll
    for (int i = 0; i < 4; i++) {
        v[i] = *(const float4*)(src + ((size_t)threadIdx.x + i*256)*4);
        s  += v[i].x + v[i].y + v[i].z + v[i].w;
        sq += v[i].x*v[i].x + v[i].y*v[i].y + v[i].z*v[i].z + v[i].w*v[i].w;
    }
    #pragma unroll
    for (int off = 16; off; off >>= 1) {
        s  += __shfl_xor_sync(~0u, s, off);
        sq += __shfl_xor_sync(~0u, sq, off);
    }
    const int warp = threadIdx.x >> 5, lane = threadIdx.x & 31;
    if (lane == 0) { red[0][warp] = s; red[1][warp] = sq; }
    __syncthreads();
    s = 0.f; sq = 0.f;
    #pragma unroll
    for (int i = 0; i < 8; i++) { s += red[0][i]; sq += red[1][i]; }
    const float mu  = s * (1.f/(float)E_);
    const float var = sq * (1.f/(float)E_) - mu*mu;
    const float rstd = rsqrtf(var + 1e-5f);
    #pragma unroll
    for (int i = 0; i < 4; i++) {
        size_t base = ((size_t)threadIdx.x + i*256)*4;
        float4 gv = *(const float4*)(gam + base);
        float4 bv = *(const float4*)(bet + base);
        float4 o;
        o.x = (v[i].x - mu)*rstd*gv.x + bv.x;
        o.y = (v[i].y - mu)*rstd*gv.y + bv.y;
        o.z = (v[i].z - mu)*rstd*gv.z + bv.z;
        o.w = (v[i].w - mu)*rstd*gv.w + bv.w;
        *(float4*)(out + (size_t)row*E_ + base) = o;
        if (WH) {
            __half2 h0 = __floats2half2_rn(o.x, o.y);
            __half2 h1 = __floats2half2_rn(o.z, o.w);
            uint2 pk; pk.x = *(unsigned*)&h0; pk.y = *(unsigned*)&h1;
            *(uint2*)(outh + (size_t)row*E_ + base) = pk;
        }
    }
}

// ---------------- launch ----------------------------------------------------
extern "C" void kernel_launch(void* const* d_in, const int* in_sizes, int n_in,
                              void* d_out, int out_size)
{
    const float* x   = (const float*)d_in[0];
    const float* wq  = (const float*)d_in[1];
    const float* bq  = (const float*)d_in[2];
    const float* wk  = (const float*)d_in[3];
    const float* bk  = (const float*)d_in[4];
    // d_in[5], d_in[6] = wv, bv — dead in the reference
    const float* wo  = (const float*)d_in[7];
    const float* bo  = (const float*)d_in[8];
    const float* w1  = (const float*)d_in[9];
    const float* b1  = (const float*)d_in[10];
    const float* w2  = (const float*)d_in[11];
    const float* b2  = (const float*)d_in[12];
    const float* g1  = (const float*)d_in[13];
    const float* be1 = (const float*)d_in[14];
    const float* g2  = (const float*)d_in[15];
    const float* be2 = (const float*)d_in[16];
    float* out = (float*)d_out;

    float *q, *k, *tmp, *x1;
    __half *xh, *attnh, *x1h, *hh, *wqh, *wkh, *woh, *w1h, *w2h;
    cudaGetSymbolAddress((void**)&q,    g_q);
    cudaGetSymbolAddress((void**)&k,    g_k);
    cudaGetSymbolAddress((void**)&tmp,  g_tmp);
    cudaGetSymbolAddress((void**)&x1,   g_x1);
    cudaGetSymbolAddress((void**)&xh,   g_xh);
    cudaGetSymbolAddress((void**)&attnh,g_attnh);
    cudaGetSymbolAddress((void**)&x1h,  g_x1h);
    cudaGetSymbolAddress((void**)&hh,   g_hh);
    cudaGetSymbolAddress((void**)&wqh,  g_wqh);
    cudaGetSymbolAddress((void**)&wkh,  g_wkh);
    cudaGetSymbolAddress((void**)&woh,  g_woh);
    cudaGetSymbolAddress((void**)&w1h,  g_w1h);
    cudaGetSymbolAddress((void**)&w2h,  g_w2h);

    cudaFuncSetAttribute(hgemm<0>, cudaFuncAttributeMaxDynamicSharedMemorySize, GSMEM);
    cudaFuncSetAttribute(hgemm<1>, cudaFuncAttributeMaxDynamicSharedMemorySize, GSMEM);
    cudaFuncSetAttribute(hgemm<2>, cudaFuncAttributeMaxDynamicSharedMemorySize, GSMEM);
    cudaFuncSetAttribute(attn_kernel, cudaFuncAttributeMaxDynamicSharedMemorySize, ATTN_SMEM);

    // fp32 -> fp16 conversions
    const int nEE8 = (E_*E_)/8, nEF8 = (E_*F_)/8, nXE8 = (BT_*E_)/8;
    f2h<<<(nXE8+255)/256, 256>>>(x,  xh,  nXE8);
    f2h<<<(nEE8+255)/256, 256>>>(wq, wqh, nEE8);
    f2h<<<(nEE8+255)/256, 256>>>(wk, wkh, nEE8);
    f2h<<<(nEE8+255)/256, 256>>>(wo, woh, nEE8);
    f2h<<<(nEF8+255)/256, 256>>>(w1, w1h, nEF8);
    f2h<<<(nEF8+255)/256, 256>>>(w2, w2h, nEF8);

    dim3 blk(512);
    // q = x@wq + bq -> (B,H,T,DK) fp32
    hgemm<0><<<dim3(32,16), blk, GSMEM>>>(xh, wqh, bq, nullptr, q, BT_, E_, E_);
    // k = x@wk + bk -> (B,H,T,DK) fp32
    hgemm<0><<<dim3(32,16), blk, GSMEM>>>(xh, wkh, bk, nullptr, k, BT_, E_, E_);
    // attn = softmax(q k^T / sqrt(DK)) -> fp16 (B,T,H*T)
    attn_kernel<<<B_*H_, 256, ATTN_SMEM>>>(q, k, attnh);
    // tmp = attn @ wo + bo + x   (fp32)
    hgemm<2><<<dim3(32,16), blk, GSMEM>>>(attnh, woh, bo, x, tmp, BT_, E_, E_);
    // x1 = LN(tmp)  (fp32 + fp16 copy)
    ln_kernel<1><<<BT_, 256>>>(tmp, g1, be1, x1, x1h);
    // h = relu(x1 @ w1 + b1) -> fp16
    hgemm<1><<<dim3(32,64), blk, GSMEM>>>(x1h, w1h, b1, nullptr, hh, BT_, F_, E_);
    // tmp = h @ w2 + b2 + x1  (fp32)
    hgemm<2><<<dim3(32,16), blk, GSMEM>>>(hh, w2h, b2, x1, tmp, BT_, E_, F_);
    // out = LN(tmp)
    ln_kernel<0><<<BT_, 256>>>(tmp, g2, be2, out, nullptr);
}

// round 17
// speedup vs baseline: 1.0002x; 1.0002x over previous
#include <cuda_runtime.h>
#include <cuda_fp16.h>
#include <cstdint>

// Problem dims
#define B_   32
#define T_   128
#define E_   4096
#define H_   32
#define DK_  128
#define F_   16384
#define BT_  (B_*T_)

// ---------------- scratch (device globals: allocation-free rule) ----------
__device__ float  g_q   [(size_t)BT_*E_];
__device__ float  g_k   [(size_t)BT_*E_];
__device__ float  g_tmp [(size_t)BT_*E_];
__device__ float  g_x1  [(size_t)BT_*E_];
__device__ __half g_xh  [(size_t)BT_*E_];
__device__ __half g_attnh[(size_t)BT_*E_];  // attention probs, (B,T,H*T) layout, fp16
__device__ __half g_x1h [(size_t)BT_*E_];
__device__ __half g_hh  [(size_t)BT_*F_];
__device__ __half g_wqh [(size_t)E_*E_];
__device__ __half g_wkh [(size_t)E_*E_];
__device__ __half g_woh [(size_t)E_*E_];
__device__ __half g_w1h [(size_t)E_*F_];
__device__ __half g_w2h [(size_t)F_*E_];

// ======================= low-level helpers =================================
__device__ __forceinline__ unsigned smem_u32(const void* p) {
    return (unsigned)__cvta_generic_to_shared(p);
}
__device__ __forceinline__ void cp_async16(unsigned dst, const void* src) {
    asm volatile("cp.async.cg.shared.global [%0], [%1], 16;\n" :: "r"(dst), "l"(src));
}
__device__ __forceinline__ void cp_commit() {
    asm volatile("cp.async.commit_group;\n" ::: "memory");
}
template<int N> __device__ __forceinline__ void cp_wait() {
    asm volatile("cp.async.wait_group %0;\n" :: "n"(N) : "memory");
}
__device__ __forceinline__ void ldsm4(unsigned* r, unsigned addr) {
    asm volatile("ldmatrix.sync.aligned.m8n8.x4.shared.b16 {%0,%1,%2,%3}, [%4];"
        : "=r"(r[0]), "=r"(r[1]), "=r"(r[2]), "=r"(r[3]) : "r"(addr));
}
__device__ __forceinline__ void ldsm4t(unsigned* r, unsigned addr) {
    asm volatile("ldmatrix.sync.aligned.m8n8.x4.trans.shared.b16 {%0,%1,%2,%3}, [%4];"
        : "=r"(r[0]), "=r"(r[1]), "=r"(r[2]), "=r"(r[3]) : "r"(addr));
}
__device__ __forceinline__ void mma16816(float* c, const unsigned* a, const unsigned* b) {
    asm volatile("mma.sync.aligned.m16n8k16.row.col.f32.f16.f16.f32 "
        "{%0,%1,%2,%3}, {%4,%5,%6,%7}, {%8,%9}, {%0,%1,%2,%3};"
        : "+f"(c[0]), "+f"(c[1]), "+f"(c[2]), "+f"(c[3])
        : "r"(a[0]), "r"(a[1]), "r"(a[2]), "r"(a[3]), "r"(b[0]), "r"(b[1]));
}
__device__ __forceinline__ unsigned sw128(unsigned o) { return o ^ ((o >> 3) & 0x70); }

// ======================= fp16 GEMM =========================================
// D[M,N] = A_h[M,K] @ W_h[K,N] (+bias fp32; EPI variants). fp32 accumulate.
// CTA tile 128x256, BK=64, 512 threads = 16 warps in 2(M)x8(N) grid of 64x32.
// SMEM: A stage 128rows x 128B (sw128), B stage 4 nh-blocks x [64rows x 128B].
// EPI: 0 = +bias, scatter fp32 to (B,H,T,DK); 1 = relu(+bias) -> fp16;
//      2 = +bias+resid(fp32) -> fp32
#define SA_SZ 16384
#define SB_SZ 32768
#define SB_BASE (3*SA_SZ)
#define GSMEM (3*SA_SZ + 3*SB_SZ)     // 147456 B

template<int EPI>
__global__ void __launch_bounds__(512, 1) hgemm(
    const __half* __restrict__ A, const __half* __restrict__ W,
    const float* __restrict__ bias, const float* __restrict__ resid,
    void* __restrict__ outp, int M, int N, int K)
{
    extern __shared__ char smem[];
    const unsigned sbase = smem_u32(smem);
    const int tid = threadIdx.x, wid = tid >> 5, lane = tid & 31;
    const int m0 = blockIdx.x * 128, n0 = blockIdx.y * 256;
    const int wm = (wid >> 3) * 64, wn = (wid & 7) * 32;
    const int KT = K >> 6;

    auto load_stage = [&](int s, int kt) {
        const int k0 = kt << 6;
        const unsigned sA = sbase + s*SA_SZ;
        const unsigned sB = sbase + SB_BASE + s*SB_SZ;
        #pragma unroll
        for (int i = 0; i < 2; i++) {               // A: 1024 granules of 16B
            int gid = tid + i*512;
            int row = gid >> 3, g = gid & 7;
            cp_async16(sA + sw128((row << 7) + (g << 4)),
                       A + (size_t)(m0 + row)*K + k0 + g*8);
        }
        #pragma unroll
        for (int i = 0; i < 4; i++) {               // B: 2048 granules
            int gid = tid + i*512;
            int k = gid >> 5, gg = gid & 31, nh = gg >> 3, g = gg & 7;
            cp_async16(sB + (nh << 13) + sw128((k << 7) + (g << 4)),
                       W + (size_t)(k0 + k)*N + n0 + nh*64 + g*8);
        }
        cp_commit();
    };

    float acc[4][4][4];
    #pragma unroll
    for (int mi = 0; mi < 4; mi++)
        #pragma unroll
        for (int ni = 0; ni < 4; ni++)
            #pragma unroll
            for (int r = 0; r < 4; r++) acc[mi][ni][r] = 0.f;

    load_stage(0, 0);
    load_stage(1, 1);

    // precomputed lane pieces for ldmatrix addressing
    const int l8  = (lane & 7) + ((lane >> 3) & 1) * 8;   // row within 16
    const int sel = (lane >> 4) & 1;                       // 0/1 -> +8 halves

    for (int kt = 0; kt < KT; kt++) {
        cp_wait<1>();
        __syncthreads();
        const int s = kt % 3;
        const unsigned sA = sbase + s*SA_SZ;
        const unsigned sB = sbase + SB_BASE + s*SB_SZ + ((wn >> 6) << 13);

        #pragma unroll
        for (int ks = 0; ks < 4; ks++) {
            unsigned a[4][4], bq[2][4];
            #pragma unroll
            for (int mi = 0; mi < 4; mi++) {
                int arow = wm + mi*16 + l8;
                int acol = ks*32 + sel*16;               // bytes
                ldsm4(a[mi], sA + sw128((arow << 7) + acol));
            }
            #pragma unroll
            for (int np = 0; np < 2; np++) {
                int brow = ks*16 + l8;
                int bcol = ((wn & 63) + np*16 + sel*8) * 2;  // bytes
                ldsm4t(bq[np], sB + sw128((brow << 7) + bcol));
            }
            #pragma unroll
            for (int mi = 0; mi < 4; mi++)
                #pragma unroll
                for (int ni = 0; ni < 4; ni++)
                    mma16816(acc[mi][ni], a[mi], &bq[ni >> 1][(ni & 1) * 2]);
        }
        if (kt + 2 < KT) load_stage((kt + 2) % 3, kt + 2);
        else cp_commit();
    }

    // ---------------- epilogue (register accs -> GMEM) ---------------------
    const int g = lane >> 2, tig = lane & 3;
    #pragma unroll
    for (int mi = 0; mi < 4; mi++) {
        #pragma unroll
        for (int ni = 0; ni < 4; ni++) {
            const int n = n0 + wn + ni*8 + 2*tig;
            const float2 bz = *(const float2*)(bias + n);
            #pragma unroll
            for (int hh = 0; hh < 2; hh++) {
                const int m = m0 + wm + mi*16 + g + hh*8;
                float v0 = acc[mi][ni][hh*2 + 0] + bz.x;
                float v1 = acc[mi][ni][hh*2 + 1] + bz.y;
                if (EPI == 0) {
                    // scatter (b,t | h,dk) -> (B,H,T,DK) fp32
                    size_t o = (((size_t)((m >> 7)*H_ + (n >> 7))*T_ + (m & 127)) << 7) + (n & 127);
                    *(float2*)((float*)outp + o) = make_float2(v0, v1);
                } else if (EPI == 1) {
                    __half2 hv = __floats2half2_rn(fmaxf(v0, 0.f), fmaxf(v1, 0.f));
                    *(__half2*)((__half*)outp + (size_t)m*N + n) = hv;
                } else {
                    size_t o = (size_t)m*N + n;
                    float2 r = *(const float2*)(resid + o);
                    *(float2*)((float*)outp + o) = make_float2(v0 + r.x, v1 + r.y);
                }
            }
        }
    }
}

// ================= fp32 -> fp16 convert ====================================
__global__ void __launch_bounds__(256) f2h(const float* __restrict__ in,
                                           __half* __restrict__ out, int n8)
{
    int i = blockIdx.x * 256 + threadIdx.x;
    if (i >= n8) return;
    const float4* p = (const float4*)(in + (size_t)i*8);
    float4 u = p[0], v = p[1];
    __half2 h0 = __floats2half2_rn(u.x, u.y);
    __half2 h1 = __floats2half2_rn(u.z, u.w);
    __half2 h2 = __floats2half2_rn(v.x, v.y);
    __half2 h3 = __floats2half2_rn(v.z, v.w);
    uint4 o;
    o.x = *(unsigned*)&h0; o.y = *(unsigned*)&h1;
    o.z = *(unsigned*)&h2; o.w = *(unsigned*)&h3;
    *(uint4*)(out + (size_t)i*8) = o;
}

// ================= attention: scores (tf32 mma.sync) + softmax =============
// q,k fp32 (B,H,T,DK); output fp16 probs in (B,T,H*T) layout.
#define ATTN_SMEM (2*128*132*4)
__device__ __forceinline__ void mma_tf32_frag(float* c, const unsigned* a, const unsigned* b) {
    asm volatile(
        "mma.sync.aligned.m16n8k8.row.col.f32.tf32.tf32.f32 "
        "{%0,%1,%2,%3}, {%4,%5,%6,%7}, {%8,%9}, {%0,%1,%2,%3};\n"
        : "+f"(c[0]), "+f"(c[1]), "+f"(c[2]), "+f"(c[3])
        : "r"(a[0]), "r"(a[1]), "r"(a[2]), "r"(a[3]), "r"(b[0]), "r"(b[1]));
}

__global__ void __launch_bounds__(256) attn_kernel(
    const float* __restrict__ q, const float* __restrict__ k, __half* __restrict__ attn)
{
    extern __shared__ float fsm[];
    float* qs = fsm;             // [128][132]
    float* ks = fsm + 128*132;   // [128][132]
    const int bh = blockIdx.x;
    const int b = bh >> 5, h = bh & 31;
    const float* qg = q + (size_t)bh * 16384;
    const float* kg = k + (size_t)bh * 16384;
    const int tid = threadIdx.x;

    for (int i = tid; i < 4096; i += 256) {
        int row = i >> 5, c4 = (i & 31) << 2;
        *(float4*)(qs + row*132 + c4) = *(const float4*)(qg + row*128 + c4);
        *(float4*)(ks + row*132 + c4) = *(const float4*)(kg + row*128 + c4);
    }
    __syncthreads();

    const int warp = tid >> 5, lane = tid & 31, g = lane >> 2, tig = lane & 3;
    const int rbase = warp * 16;

    float acc[16][4];
    #pragma unroll
    for (int ni = 0; ni < 16; ni++)
        #pragma unroll
        for (int r = 0; r < 4; r++) acc[ni][r] = 0.f;

    #pragma unroll
    for (int kk = 0; kk < 16; ++kk) {
        const int kb = kk * 8;
        unsigned a[4];
        a[0] = __float_as_uint(qs[(rbase + g)*132 + kb + tig]);
        a[1] = __float_as_uint(qs[(rbase + g + 8)*132 + kb + tig]);
        a[2] = __float_as_uint(qs[(rbase + g)*132 + kb + tig + 4]);
        a[3] = __float_as_uint(qs[(rbase + g + 8)*132 + kb + tig + 4]);
        #pragma unroll
        for (int ni = 0; ni < 16; ++ni) {
            int c = ni*8 + g;
            unsigned bfr[2];
            bfr[0] = __float_as_uint(ks[c*132 + kb + tig]);
            bfr[1] = __float_as_uint(ks[c*132 + kb + tig + 4]);
            mma_tf32_frag(acc[ni], a, bfr);
        }
    }

    #pragma unroll
    for (int ni = 0; ni < 16; ni++) {
        int c = ni*8 + 2*tig;
        qs[(rbase + g)*132 + c]       = acc[ni][0];
        qs[(rbase + g)*132 + c + 1]   = acc[ni][1];
        qs[(rbase + g + 8)*132 + c]   = acc[ni][2];
        qs[(rbase + g + 8)*132 + c+1] = acc[ni][3];
    }
    __syncwarp();

    const float SCALE = 0.0883883476483184406f;   // 1/sqrt(128)
    for (int r = 0; r < 16; ++r) {
        int row = rbase + r;
        float v0 = qs[row*132 + lane]      * SCALE;
        float v1 = qs[row*132 + lane + 32] * SCALE;
        float v2 = qs[row*132 + lane + 64] * SCALE;
        float v3 = qs[row*132 + lane + 96] * SCALE;
        float mx = fmaxf(fmaxf(v0, v1), fmaxf(v2, v3));
        #pragma unroll
        for (int off = 16; off; off >>= 1) mx = fmaxf(mx, __shfl_xor_sync(~0u, mx, off));
        float e0 = __expf(v0 - mx), e1 = __expf(v1 - mx), e2 = __expf(v2 - mx), e3 = __expf(v3 - mx);
        float s = e0 + e1 + e2 + e3;
        #pragma unroll
        for (int off = 16; off; off >>= 1) s += __shfl_xor_sync(~0u, s, off);
        float inv = __frcp_rn(s);
        // (B,T,H,T') layout, fp16
        __half* o = attn + (((size_t)(b*T_ + row)*H_ + h) << 7);
        o[lane]      = __float2half_rn(e0*inv);
        o[lane + 32] = __float2half_rn(e1*inv);
        o[lane + 64] = __float2half_rn(e2*inv);
        o[lane + 96] = __float2half_rn(e3*inv);
    }
}

// ---------------- layernorm (one CTA per token) ----------------------------
// WH=1: additionally write fp16 copy (for the next GEMM's A operand).
template<int WH>
__global__ void __launch_bounds__(256) ln_kernel(
    const float* __restrict__ in, const float* __restrict__ gam,
    const float* __restrict__ bet, float* __restrict__ out, __half* __restrict__ outh)
{
    __shared__ float red[2][8];
    const int row = blockIdx.x;
    const float* src = in + (size_t)row * E_;
    float4 v[4];
    float s = 0.f, sq = 0.f;
    #pragma unroll
    for (int i = 0; i < 4; i++) {
        v[i] = *(const float4*)(src + ((size_t)threadIdx.x + i*256)*4);
        s  += v[i].x + v[i].y + v[i].z + v[i].w;
        sq += v[i].x*v[i].x + v[i].y*v[i].y + v[i].z*v[i].z + v[i].w*v[i].w;
    }
    #pragma unroll
    for (int off = 16; off; off >>= 1) {
        s  += __shfl_xor_sync(~0u, s, off);
        sq += __shfl_xor_sync(~0u, sq, off);
    }
    const int warp = threadIdx.x >> 5, lane = threadIdx.x & 31;
    if (lane == 0) { red[0][warp] = s; red[1][warp] = sq; }
    __syncthreads();
    s = 0.f; sq = 0.f;
    #pragma unroll
    for (int i = 0; i < 8; i++) { s += red[0][i]; sq += red[1][i]; }
    const float mu  = s * (1.f/(float)E_);
    const float var = sq * (1.f/(float)E_) - mu*mu;
    const float rstd = rsqrtf(var + 1e-5f);
    #pragma unroll
    for (int i = 0; i < 4; i++) {
        size_t base = ((size_t)threadIdx.x + i*256)*4;
        float4 gv = *(const float4*)(gam + base);
        float4 bv = *(const float4*)(bet + base);
        float4 o;
        o.x = (v[i].x - mu)*rstd*gv.x + bv.x;
        o.y = (v[i].y - mu)*rstd*gv.y + bv.y;
        o.z = (v[i].z - mu)*rstd*gv.z + bv.z;
        o.w = (v[i].w - mu)*rstd*gv.w + bv.w;
        *(float4*)(out + (size_t)row*E_ + base) = o;
        if (WH) {
            __half2 h0 = __floats2half2_rn(o.x, o.y);
            __half2 h1 = __floats2half2_rn(o.z, o.w);
            uint2 pk; pk.x = *(unsigned*)&h0; pk.y = *(unsigned*)&h1;
            *(uint2*)(outh + (size_t)row*E_ + base) = pk;
        }
    }
}

// ---------------- launch ----------------------------------------------------
extern "C" void kernel_launch(void* const* d_in, const int* in_sizes, int n_in,
                              void* d_out, int out_size)
{
    const float* x   = (const float*)d_in[0];
    const float* wq  = (const float*)d_in[1];
    const float* bq  = (const float*)d_in[2];
    const float* wk  = (const float*)d_in[3];
    const float* bk  = (const float*)d_in[4];
    // d_in[5], d_in[6] = wv, bv — dead in the reference
    const float* wo  = (const float*)d_in[7];
    const float* bo  = (const float*)d_in[8];
    const float* w1  = (const float*)d_in[9];
    const float* b1  = (const float*)d_in[10];
    const float* w2  = (const float*)d_in[11];
    const float* b2  = (const float*)d_in[12];
    const float* g1  = (const float*)d_in[13];
    const float* be1 = (const float*)d_in[14];
    const float* g2  = (const float*)d_in[15];
    const float* be2 = (const float*)d_in[16];
    float* out = (float*)d_out;

    float *q, *k, *tmp, *x1;
    __half *xh, *attnh, *x1h, *hh, *wqh, *wkh, *woh, *w1h, *w2h;
    cudaGetSymbolAddress((void**)&q,    g_q);
    cudaGetSymbolAddress((void**)&k,    g_k);
    cudaGetSymbolAddress((void**)&tmp,  g_tmp);
    cudaGetSymbolAddress((void**)&x1,   g_x1);
    cudaGetSymbolAddress((void**)&xh,   g_xh);
    cudaGetSymbolAddress((void**)&attnh,g_attnh);
    cudaGetSymbolAddress((void**)&x1h,  g_x1h);
    cudaGetSymbolAddress((void**)&hh,   g_hh);
    cudaGetSymbolAddress((void**)&wqh,  g_wqh);
    cudaGetSymbolAddress((void**)&wkh,  g_wkh);
    cudaGetSymbolAddress((void**)&woh,  g_woh);
    cudaGetSymbolAddress((void**)&w1h,  g_w1h);
    cudaGetSymbolAddress((void**)&w2h,  g_w2h);

    cudaFuncSetAttribute(hgemm<0>, cudaFuncAttributeMaxDynamicSharedMemorySize, GSMEM);
    cudaFuncSetAttribute(hgemm<1>, cudaFuncAttributeMaxDynamicSharedMemorySize, GSMEM);
    cudaFuncSetAttribute(hgemm<2>, cudaFuncAttributeMaxDynamicSharedMemorySize, GSMEM);
    cudaFuncSetAttribute(attn_kernel, cudaFuncAttributeMaxDynamicSharedMemorySize, ATTN_SMEM);

    // fp32 -> fp16 conversions
    const int nEE8 = (E_*E_)/8, nEF8 = (E_*F_)/8, nXE8 = (BT_*E_)/8;
    f2h<<<(nXE8+255)/256, 256>>>(x,  xh,  nXE8);
    f2h<<<(nEE8+255)/256, 256>>>(wq, wqh, nEE8);
    f2h<<<(nEE8+255)/256, 256>>>(wk, wkh, nEE8);
    f2h<<<(nEE8+255)/256, 256>>>(wo, woh, nEE8);
    f2h<<<(nEF8+255)/256, 256>>>(w1, w1h, nEF8);
    f2h<<<(nEF8+255)/256, 256>>>(w2, w2h, nEF8);

    dim3 blk(512);
    // q = x@wq + bq -> (B,H,T,DK) fp32
    hgemm<0><<<dim3(32,16), blk, GSMEM>>>(xh, wqh, bq, nullptr, q, BT_, E_, E_);
    // k = x@wk + bk -> (B,H,T,DK) fp32
    hgemm<0><<<dim3(32,16), blk, GSMEM>>>(xh, wkh, bk, nullptr, k, BT_, E_, E_);
    // attn = softmax(q k^T / sqrt(DK)) -> fp16 (B,T,H*T)
    attn_kernel<<<B_*H_, 256, ATTN_SMEM>>>(q, k, attnh);
    // tmp = attn @ wo + bo + x   (fp32)
    hgemm<2><<<dim3(32,16), blk, GSMEM>>>(attnh, woh, bo, x, tmp, BT_, E_, E_);
    // x1 = LN(tmp)  (fp32 + fp16 copy)
    ln_kernel<1><<<BT_, 256>>>(tmp, g1, be1, x1, x1h);
    // h = relu(x1 @ w1 + b1) -> fp16
    hgemm<1><<<dim3(32,64), blk, GSMEM>>>(x1h, w1h, b1, nullptr, hh, BT_, F_, E_);
    // tmp = h @ w2 + b2 + x1  (fp32)
    hgemm<2><<<dim3(32,16), blk, GSMEM>>>(hh, w2h, b2, x1, tmp, BT_, E_, F_);
    // out = LN(tmp)
    ln_kernel<0><<<BT_, 256>>>(tmp, g2, be2, out, nullptr);
}